// round 9
// baseline (speedup 1.0000x reference)
#include <cuda_runtime.h>
#include <cuda_bf16.h>
#include <math_constants.h>
#include <cstdint>

#define B_DIM 64
#define S_DIM 512
#define H_DIM 4096
#define THREADS 256
#define WARPS 8
#define ROWS_PER_BLOCK 16
#define CHUNKS_PER_BATCH (S_DIM / ROWS_PER_BLOCK)   // 32 blocks per batch
#define CHUNK_FLOATS 512                            // per-row K-chunk
#define CHUNK_BYTES (CHUNK_FLOATS * 4)              // 2048
#define NCHUNK (H_DIM / CHUNK_FLOATS)               // 8
#define NSTAGE 4
#define STAGE_BYTES (ROWS_PER_BLOCK * CHUNK_BYTES)  // 32 KB
#define SMEM_BYTES (NSTAGE * STAGE_BYTES)           // 128 KB dynamic

// Scratch (no cudaMalloc allowed)
__device__ float        g_energies[B_DIM * S_DIM];
__device__ unsigned int g_counter[B_DIM];

__device__ __forceinline__ uint32_t smem_u32(const void* p) {
    return (uint32_t)__cvta_generic_to_shared(p);
}

__device__ __forceinline__ void mbar_init(uint32_t mbar, uint32_t count) {
    asm volatile("mbarrier.init.shared.b64 [%0], %1;" :: "r"(mbar), "r"(count) : "memory");
}
__device__ __forceinline__ void mbar_expect_tx(uint32_t mbar, uint32_t bytes) {
    asm volatile("mbarrier.arrive.expect_tx.shared.b64 _, [%0], %1;"
                 :: "r"(mbar), "r"(bytes) : "memory");
}
__device__ __forceinline__ void bulk_g2s(uint32_t dst, const void* src,
                                         uint32_t bytes, uint32_t mbar) {
    asm volatile(
        "cp.async.bulk.shared::cluster.global.mbarrier::complete_tx::bytes "
        "[%0], [%1], %2, [%3];"
        :: "r"(dst), "l"(src), "r"(bytes), "r"(mbar) : "memory");
}
__device__ __forceinline__ void mbar_wait(uint32_t mbar, uint32_t phase) {
    uint32_t done;
    asm volatile(
        "{\n\t.reg .pred p;\n\t"
        "mbarrier.try_wait.parity.shared.b64 p, [%1], %2;\n\t"
        "selp.b32 %0, 1, 0, p;\n\t}"
        : "=r"(done) : "r"(mbar), "r"(phase) : "memory");
    while (!done) {
        asm volatile(
            "{\n\t.reg .pred p;\n\t"
            "mbarrier.try_wait.parity.shared.b64 p, [%1], %2;\n\t"
            "selp.b32 %0, 1, 0, p;\n\t}"
            : "=r"(done) : "r"(mbar), "r"(phase) : "memory");
    }
}

__global__ __launch_bounds__(THREADS)
void fused_kernel(const float* __restrict__ questions,
                  const float* __restrict__ facts,
                  float* __restrict__ out) {
    extern __shared__ __align__(128) char tiles[];   // NSTAGE x 32 KB
    __shared__ uint64_t mbar_full[NSTAGE];
    __shared__ float red[WARPS];
    __shared__ float bcast;
    __shared__ int   is_last;

    const int tid  = threadIdx.x;
    const int warp = tid >> 5;
    const int lane = tid & 31;

    const int b  = blockIdx.x / CHUNKS_PER_BATCH;
    const int s0 = (blockIdx.x % CHUNKS_PER_BATCH) * ROWS_PER_BLOCK;

    // gmem base of this block's 16 rows (contiguous 256 KB region)
    const char* gbase = reinterpret_cast<const char*>(
        facts + ((size_t)b * S_DIM + s0) * H_DIM);
    const float4* qv = reinterpret_cast<const float4*>(
        questions + (size_t)b * H_DIM);

    // init full-barriers (one expected arrival: the expect_tx by thread 0)
    if (tid == 0) {
        #pragma unroll
        for (int s = 0; s < NSTAGE; ++s)
            mbar_init(smem_u32(&mbar_full[s]), 1);
    }
    __syncthreads();

    // prologue: fill the pipeline
    if (tid == 0) {
        #pragma unroll
        for (int s = 0; s < NSTAGE; ++s) {
            uint32_t mb = smem_u32(&mbar_full[s]);
            mbar_expect_tx(mb, STAGE_BYTES);
            uint32_t dst = smem_u32(tiles + s * STAGE_BYTES);
            #pragma unroll
            for (int r = 0; r < ROWS_PER_BLOCK; ++r)
                bulk_g2s(dst + r * CHUNK_BYTES,
                         gbase + (size_t)r * (H_DIM * 4) + (size_t)s * CHUNK_BYTES,
                         CHUNK_BYTES, mb);
        }
    }

    // mainloop: each warp owns rows 2*warp, 2*warp+1
    const int r0 = 2 * warp;
    const int r1 = 2 * warp + 1;
    float a00 = 0.f, a01 = 0.f, a02 = 0.f, a03 = 0.f;   // row0 partials (k=0..3)
    float a10 = 0.f, a11 = 0.f, a12 = 0.f, a13 = 0.f;   // row1 partials

    for (int c = 0; c < NCHUNK; ++c) {
        const int stage = c & (NSTAGE - 1);
        const uint32_t phase = (c >> 2) & 1;
        mbar_wait(smem_u32(&mbar_full[stage]), phase);

        const char* base = tiles + stage * STAGE_BYTES;
        const float4* f0p = reinterpret_cast<const float4*>(base + r0 * CHUNK_BYTES);
        const float4* f1p = reinterpret_cast<const float4*>(base + r1 * CHUNK_BYTES);
        const float4* qp  = qv + c * (CHUNK_FLOATS / 4);

        #pragma unroll
        for (int k = 0; k < 4; ++k) {
            const int idx = k * 32 + lane;
            float4 q  = __ldg(&qp[idx]);
            float4 f0 = f0p[idx];
            float4 f1 = f1p[idx];
            float d0 = fmaf(f0.x, q.x, fmaf(f0.y, q.y, fmaf(f0.z, q.z, f0.w * q.w)));
            float d1 = fmaf(f1.x, q.x, fmaf(f1.y, q.y, fmaf(f1.z, q.z, f1.w * q.w)));
            if (k == 0) { a00 += d0; a10 += d1; }
            else if (k == 1) { a01 += d0; a11 += d1; }
            else if (k == 2) { a02 += d0; a12 += d1; }
            else { a03 += d0; a13 += d1; }
        }

        __syncthreads();   // everyone done reading this stage buffer
        if (tid == 0 && c + NSTAGE < NCHUNK) {
            const int nc = c + NSTAGE;
            uint32_t mb = smem_u32(&mbar_full[stage]);
            mbar_expect_tx(mb, STAGE_BYTES);
            uint32_t dst = smem_u32(tiles + stage * STAGE_BYTES);
            #pragma unroll
            for (int r = 0; r < ROWS_PER_BLOCK; ++r)
                bulk_g2s(dst + r * CHUNK_BYTES,
                         gbase + (size_t)r * (H_DIM * 4) + (size_t)nc * CHUNK_BYTES,
                         CHUNK_BYTES, mb);
        }
    }

    // reduce and write energies
    float acc0 = (a00 + a01) + (a02 + a03);
    float acc1 = (a10 + a11) + (a12 + a13);
    #pragma unroll
    for (int off = 16; off > 0; off >>= 1) {
        acc0 += __shfl_xor_sync(0xffffffffu, acc0, off);
        acc1 += __shfl_xor_sync(0xffffffffu, acc1, off);
    }
    if (lane == 0) {
        g_energies[b * S_DIM + s0 + r0] = acc0;
        g_energies[b * S_DIM + s0 + r1] = acc1;
    }

    // ---- publish: last block of this batch performs the softmax ----
    __threadfence();
    __syncthreads();
    if (tid == 0) {
        unsigned prev = atomicAdd(&g_counter[b], 1u);
        is_last = (prev == CHUNKS_PER_BATCH - 1);
        if (is_last) {
            g_counter[b] = 0;
            __threadfence();
        }
    }
    __syncthreads();
    if (!is_last) return;

    // ---- softmax over the batch's 512 energies (2 elems/thread) ----
    float e0 = __ldcg(&g_energies[b * S_DIM + tid]);
    float e1 = __ldcg(&g_energies[b * S_DIM + tid + THREADS]);

    float m = fmaxf(e0, e1);
    #pragma unroll
    for (int off = 16; off > 0; off >>= 1)
        m = fmaxf(m, __shfl_xor_sync(0xffffffffu, m, off));
    if (lane == 0) red[warp] = m;
    __syncthreads();
    if (tid < 32) {
        float v = (lane < WARPS) ? red[lane] : -CUDART_INF_F;
        #pragma unroll
        for (int off = 16; off > 0; off >>= 1)
            v = fmaxf(v, __shfl_xor_sync(0xffffffffu, v, off));
        if (lane == 0) bcast = v;
    }
    __syncthreads();
    const float row_max = bcast;

    float x0 = __expf(e0 - row_max);
    float x1 = __expf(e1 - row_max);
    float ssum = x0 + x1;
    #pragma unroll
    for (int off = 16; off > 0; off >>= 1)
        ssum += __shfl_xor_sync(0xffffffffu, ssum, off);
    __syncthreads();
    if (lane == 0) red[warp] = ssum;
    __syncthreads();
    if (tid < 32) {
        float v = (lane < WARPS) ? red[lane] : 0.f;
        #pragma unroll
        for (int off = 16; off > 0; off >>= 1)
            v += __shfl_xor_sync(0xffffffffu, v, off);
        if (lane == 0) bcast = v;
    }
    __syncthreads();
    const float inv = 1.0f / bcast;

    out[b * S_DIM + tid]           = x0 * inv;
    out[b * S_DIM + tid + THREADS] = x1 * inv;
}

extern "C" void kernel_launch(void* const* d_in, const int* in_sizes, int n_in,
                              void* d_out, int out_size) {
    const float* questions = (const float*)d_in[0];
    const float* facts     = (const float*)d_in[1];
    if (n_in >= 2 && in_sizes[0] > in_sizes[1]) {   // facts is the big one
        questions = (const float*)d_in[1];
        facts     = (const float*)d_in[0];
    }
    float* out = (float*)d_out;

    // 128 KB dynamic smem: raise the opt-in limit (idempotent, capture-safe)
    cudaFuncSetAttribute(fused_kernel,
                         cudaFuncAttributeMaxDynamicSharedMemorySize, SMEM_BYTES);

    fused_kernel<<<B_DIM * CHUNKS_PER_BATCH, THREADS, SMEM_BYTES>>>(
        questions, facts, out);
}

// round 10
// speedup vs baseline: 1.4514x; 1.4514x over previous
#include <cuda_runtime.h>
#include <cuda_bf16.h>
#include <math_constants.h>

#define B_DIM 64
#define S_DIM 512
#define H_DIM 4096
#define WARPS_PER_BLOCK 16
#define THREADS (WARPS_PER_BLOCK * 32)            // 512
#define S_PER_BLOCK 32                            // each warp handles 2 s-rows
#define CHUNKS (S_DIM / S_PER_BLOCK)              // 16 blocks per batch

// Scratch (no cudaMalloc allowed)
__device__ float        g_energies[B_DIM * S_DIM];
__device__ unsigned int g_counter[B_DIM];   // zero-init; reset by finishing block

__global__ __launch_bounds__(THREADS)       // 512 thr -> ptxas caps at 128 regs
void fused_kernel(const float* __restrict__ questions,
                  const float* __restrict__ facts,
                  float* __restrict__ out) {
    __shared__ float4 sq[H_DIM / 4];          // 16 KB question row
    __shared__ float  red[WARPS_PER_BLOCK];
    __shared__ float  bcast;
    __shared__ int    is_last;

    const int b      = blockIdx.x / CHUNKS;
    const int schunk = blockIdx.x % CHUNKS;
    const int tid    = threadIdx.x;
    const int warp   = tid >> 5;
    const int lane   = tid & 31;

    // Stage question row for this batch into shared memory (coalesced float4)
    const float4* qv = reinterpret_cast<const float4*>(questions + (size_t)b * H_DIM);
    #pragma unroll
    for (int i = tid; i < H_DIM / 4; i += THREADS)
        sq[i] = qv[i];
    __syncthreads();

    // ---- energies: EXACT R1 inner loop (plain loads, full unroll) ----
    #pragma unroll
    for (int t = 0; t < S_PER_BLOCK / WARPS_PER_BLOCK; ++t) {
        const int s = schunk * S_PER_BLOCK + t * WARPS_PER_BLOCK + warp;
        const float4* fv = reinterpret_cast<const float4*>(
            facts + ((size_t)b * S_DIM + s) * H_DIM);

        float a0 = 0.f, a1 = 0.f, a2 = 0.f, a3 = 0.f;
        #pragma unroll
        for (int j = 0; j < (H_DIM / 4) / 32; j += 4) {
            float4 f0 = fv[(j + 0) * 32 + lane];
            float4 f1 = fv[(j + 1) * 32 + lane];
            float4 f2 = fv[(j + 2) * 32 + lane];
            float4 f3 = fv[(j + 3) * 32 + lane];
            float4 q0 = sq[(j + 0) * 32 + lane];
            float4 q1 = sq[(j + 1) * 32 + lane];
            float4 q2 = sq[(j + 2) * 32 + lane];
            float4 q3 = sq[(j + 3) * 32 + lane];
            a0 = fmaf(f0.x, q0.x, fmaf(f0.y, q0.y, fmaf(f0.z, q0.z, fmaf(f0.w, q0.w, a0))));
            a1 = fmaf(f1.x, q1.x, fmaf(f1.y, q1.y, fmaf(f1.z, q1.z, fmaf(f1.w, q1.w, a1))));
            a2 = fmaf(f2.x, q2.x, fmaf(f2.y, q2.y, fmaf(f2.z, q2.z, fmaf(f2.w, q2.w, a2))));
            a3 = fmaf(f3.x, q3.x, fmaf(f3.y, q3.y, fmaf(f3.z, q3.z, fmaf(f3.w, q3.w, a3))));
        }
        float acc = (a0 + a1) + (a2 + a3);

        #pragma unroll
        for (int off = 16; off > 0; off >>= 1)
            acc += __shfl_xor_sync(0xffffffffu, acc, off);

        if (lane == 0)
            g_energies[b * S_DIM + s] = acc;
    }

    // ---- publish: last block of this batch performs the softmax ----
    __threadfence();
    __syncthreads();
    if (tid == 0) {
        unsigned prev = atomicAdd(&g_counter[b], 1u);
        is_last = (prev == CHUNKS - 1);
        if (is_last) {
            g_counter[b] = 0;        // reset for next graph replay
            __threadfence();
        }
    }
    __syncthreads();
    if (!is_last) return;

    // ---- softmax over the batch's 512 energies (512 threads, 1 elem each) ----
    float e = __ldcg(&g_energies[b * S_DIM + tid]);

    float m = e;
    #pragma unroll
    for (int off = 16; off > 0; off >>= 1)
        m = fmaxf(m, __shfl_xor_sync(0xffffffffu, m, off));
    if (lane == 0) red[warp] = m;
    __syncthreads();
    if (tid < 32) {
        float v = (lane < WARPS_PER_BLOCK) ? red[lane] : -CUDART_INF_F;
        #pragma unroll
        for (int off = 16; off > 0; off >>= 1)
            v = fmaxf(v, __shfl_xor_sync(0xffffffffu, v, off));
        if (lane == 0) bcast = v;
    }
    __syncthreads();
    const float row_max = bcast;

    float x = __expf(e - row_max);
    float ssum = x;
    #pragma unroll
    for (int off = 16; off > 0; off >>= 1)
        ssum += __shfl_xor_sync(0xffffffffu, ssum, off);
    __syncthreads();
    if (lane == 0) red[warp] = ssum;
    __syncthreads();
    if (tid < 32) {
        float v = (lane < WARPS_PER_BLOCK) ? red[lane] : 0.f;
        #pragma unroll
        for (int off = 16; off > 0; off >>= 1)
            v += __shfl_xor_sync(0xffffffffu, v, off);
        if (lane == 0) bcast = v;
    }
    __syncthreads();

    out[b * S_DIM + tid] = x / bcast;
}

extern "C" void kernel_launch(void* const* d_in, const int* in_sizes, int n_in,
                              void* d_out, int out_size) {
    const float* questions = (const float*)d_in[0];
    const float* facts     = (const float*)d_in[1];
    if (n_in >= 2 && in_sizes[0] > in_sizes[1]) {   // facts is the big one
        questions = (const float*)d_in[1];
        facts     = (const float*)d_in[0];
    }
    float* out = (float*)d_out;

    fused_kernel<<<B_DIM * CHUNKS, THREADS>>>(questions, facts, out);
}

// round 11
// speedup vs baseline: 1.6301x; 1.1232x over previous
#include <cuda_runtime.h>
#include <cuda_bf16.h>
#include <math_constants.h>

#define B_DIM 64
#define S_DIM 512
#define H_DIM 4096
#define WARPS_PER_BLOCK 8
#define THREADS (WARPS_PER_BLOCK * 32)            // 256
#define ROWS_PER_WARP 2
#define ROWS_PER_TILE (WARPS_PER_BLOCK * ROWS_PER_WARP)  // 16
#define TILES_PER_BATCH (S_DIM / ROWS_PER_TILE)          // 32
#define N_TILES (B_DIM * TILES_PER_BATCH)                // 2048
#define GRID 444                                          // 148 SMs * 3 CTAs, one wave

// Scratch (no cudaMalloc allowed)
__device__ float        g_energies[B_DIM * S_DIM];
__device__ unsigned int g_counter[B_DIM];   // zero-init; reset by finishing block

__global__ __launch_bounds__(THREADS, 3)
void fused_kernel(const float* __restrict__ questions,
                  const float* __restrict__ facts,
                  float* __restrict__ out) {
    __shared__ float red[WARPS_PER_BLOCK];
    __shared__ float bcast;
    __shared__ int   is_last;

    const int tid  = threadIdx.x;
    const int warp = tid >> 5;
    const int lane = tid & 31;

    // Contiguous tile range for this CTA (balanced within +/-1 tile)
    const int t_begin = (int)(((long long)blockIdx.x     * N_TILES) / GRID);
    const int t_end   = (int)(((long long)(blockIdx.x+1) * N_TILES) / GRID);

    for (int tile = t_begin; tile < t_end; ++tile) {
        const int b     = tile / TILES_PER_BATCH;
        const int chunk = tile % TILES_PER_BATCH;

        // q row read through the read-only/L1 path (L2-resident: 1 MB total)
        const float4* qv = reinterpret_cast<const float4*>(
            questions + (size_t)b * H_DIM);

        // ---- energies: proven R3/R7 inner loop ----
        #pragma unroll
        for (int t = 0; t < ROWS_PER_WARP; ++t) {
            const int s = chunk * ROWS_PER_TILE + t * WARPS_PER_BLOCK + warp;
            const float4* fv = reinterpret_cast<const float4*>(
                facts + ((size_t)b * S_DIM + s) * H_DIM);

            float a0 = 0.f, a1 = 0.f, a2 = 0.f, a3 = 0.f;
            #pragma unroll 2
            for (int j = 0; j < (H_DIM / 4) / 32; j += 4) {
                float4 f0 = __ldcs(&fv[(j + 0) * 32 + lane]);
                float4 f1 = __ldcs(&fv[(j + 1) * 32 + lane]);
                float4 f2 = __ldcs(&fv[(j + 2) * 32 + lane]);
                float4 f3 = __ldcs(&fv[(j + 3) * 32 + lane]);
                float4 q0 = __ldg(&qv[(j + 0) * 32 + lane]);
                float4 q1 = __ldg(&qv[(j + 1) * 32 + lane]);
                float4 q2 = __ldg(&qv[(j + 2) * 32 + lane]);
                float4 q3 = __ldg(&qv[(j + 3) * 32 + lane]);
                a0 = fmaf(f0.x, q0.x, fmaf(f0.y, q0.y, fmaf(f0.z, q0.z, fmaf(f0.w, q0.w, a0))));
                a1 = fmaf(f1.x, q1.x, fmaf(f1.y, q1.y, fmaf(f1.z, q1.z, fmaf(f1.w, q1.w, a1))));
                a2 = fmaf(f2.x, q2.x, fmaf(f2.y, q2.y, fmaf(f2.z, q2.z, fmaf(f2.w, q2.w, a2))));
                a3 = fmaf(f3.x, q3.x, fmaf(f3.y, q3.y, fmaf(f3.z, q3.z, fmaf(f3.w, q3.w, a3))));
            }
            float acc = (a0 + a1) + (a2 + a3);
            #pragma unroll
            for (int off = 16; off > 0; off >>= 1)
                acc += __shfl_xor_sync(0xffffffffu, acc, off);
            if (lane == 0)
                g_energies[b * S_DIM + s] = acc;
        }

        // ---- publish this tile; last finisher of batch b runs the softmax ----
        __threadfence();
        __syncthreads();
        if (tid == 0) {
            unsigned prev = atomicAdd(&g_counter[b], 1u);
            is_last = (prev == TILES_PER_BATCH - 1);
            if (is_last) {
                g_counter[b] = 0;       // reset for next graph replay
                __threadfence();
            }
        }
        __syncthreads();

        if (is_last) {
            // softmax over this batch's 512 energies (256 threads, 2 elems each)
            const int base = b * S_DIM;
            float e0 = __ldcg(&g_energies[base + tid]);
            float e1 = __ldcg(&g_energies[base + tid + THREADS]);

            float m = fmaxf(e0, e1);
            #pragma unroll
            for (int off = 16; off > 0; off >>= 1)
                m = fmaxf(m, __shfl_xor_sync(0xffffffffu, m, off));
            if (lane == 0) red[warp] = m;
            __syncthreads();
            if (tid < 32) {
                float v = (lane < WARPS_PER_BLOCK) ? red[lane] : -CUDART_INF_F;
                #pragma unroll
                for (int off = 16; off > 0; off >>= 1)
                    v = fmaxf(v, __shfl_xor_sync(0xffffffffu, v, off));
                if (lane == 0) bcast = v;
            }
            __syncthreads();
            const float row_max = bcast;

            float x0 = __expf(e0 - row_max);
            float x1 = __expf(e1 - row_max);
            float ssum = x0 + x1;
            #pragma unroll
            for (int off = 16; off > 0; off >>= 1)
                ssum += __shfl_xor_sync(0xffffffffu, ssum, off);
            __syncthreads();
            if (lane == 0) red[warp] = ssum;
            __syncthreads();
            if (tid < 32) {
                float v = (lane < WARPS_PER_BLOCK) ? red[lane] : 0.f;
                #pragma unroll
                for (int off = 16; off > 0; off >>= 1)
                    v += __shfl_xor_sync(0xffffffffu, v, off);
                if (lane == 0) bcast = v;
            }
            __syncthreads();
            const float inv = 1.0f / bcast;

            out[base + tid]           = x0 * inv;
            out[base + tid + THREADS] = x1 * inv;
            __syncthreads();   // protect red/bcast before next tile
        }
    }
}

extern "C" void kernel_launch(void* const* d_in, const int* in_sizes, int n_in,
                              void* d_out, int out_size) {
    const float* questions = (const float*)d_in[0];
    const float* facts     = (const float*)d_in[1];
    if (n_in >= 2 && in_sizes[0] > in_sizes[1]) {   // facts is the big one
        questions = (const float*)d_in[1];
        facts     = (const float*)d_in[0];
    }
    float* out = (float*)d_out;

    fused_kernel<<<GRID, THREADS>>>(questions, facts, out);
}